// round 6
// baseline (speedup 1.0000x reference)
#include <cuda_runtime.h>
#include <math.h>
#include <float.h>

#define NB      64
#define TOKENS  784
#define DIM     768
#define FH      28
#define IMG     448
#define TOPK    8
#define PATCH   16

__device__ float g_dist[NB * TOKENS];
__device__ int   g_box[NB][4];   // x0, x1, y0, y1

// ---------------------------------------------------------------------------
// Kernel 1: score = dot(g, l) / ||l||  (g-norm positive per-batch constant
// -> same ordering as cosine). grid (64,49) x 256, 2 rows per warp.
// ---------------------------------------------------------------------------
__global__ void __launch_bounds__(256) sim_kernel(const float* __restrict__ x) {
    int b = blockIdx.x;
    int s = blockIdx.y;                       // 0..48 -> 16 rows per block
    const float* xb = x + (size_t)b * 785 * DIM;

    __shared__ float4 g_sh[DIM / 4];          // CLS token, 3 KB
    int tid = threadIdx.x;
    if (tid < DIM / 4) g_sh[tid] = ((const float4*)xb)[tid];
    __syncthreads();

    int warp = tid >> 5, lane = tid & 31;
    int r = s * 16 + warp * 2;                // this warp's row pair
    const float4* l0 = (const float4*)(xb + (size_t)(1 + r) * DIM);
    const float4* l1 = (const float4*)(xb + (size_t)(2 + r) * DIM);
    float d0 = 0.f, n0 = 0.f, d1 = 0.f, n1 = 0.f;
#pragma unroll
    for (int j = 0; j < 6; ++j) {
        float4 a = l0[lane + 32 * j];
        float4 c = l1[lane + 32 * j];
        float4 g = g_sh[lane + 32 * j];
        d0 += a.x * g.x + a.y * g.y + a.z * g.z + a.w * g.w;
        n0 += a.x * a.x + a.y * a.y + a.z * a.z + a.w * a.w;
        d1 += c.x * g.x + c.y * g.y + c.z * g.z + c.w * g.w;
        n1 += c.x * c.x + c.y * c.y + c.z * c.z + c.w * c.w;
    }
#pragma unroll
    for (int off = 16; off; off >>= 1) {
        d0 += __shfl_xor_sync(0xffffffffu, d0, off);
        n0 += __shfl_xor_sync(0xffffffffu, n0, off);
        d1 += __shfl_xor_sync(0xffffffffu, d1, off);
        n1 += __shfl_xor_sync(0xffffffffu, n1, off);
    }
    if (lane == 0) {
        g_dist[b * TOKENS + r]     = d0 / fmaxf(sqrtf(n0), 1e-8f);
        g_dist[b * TOKENS + r + 1] = d1 / fmaxf(sqrtf(n1), 1e-8f);
    }
}

// ---------------------------------------------------------------------------
// Kernel 2: top-8 argmax rounds (stable ties -> lower index), bounding box.
// ---------------------------------------------------------------------------
__global__ void topk_kernel() {
    int b = blockIdx.x;
    int lane = threadIdx.x;                   // 32 threads
    __shared__ float dist[TOKENS];
    for (int i = lane; i < TOKENS; i += 32) dist[i] = g_dist[b * TOKENS + i];
    __syncwarp();

    int minx = FH, maxx = -1, miny = FH, maxy = -1;
#pragma unroll 1
    for (int k = 0; k < TOPK; ++k) {
        float best = -FLT_MAX; int bi = TOKENS;
        for (int i = lane; i < TOKENS; i += 32) {
            float v = dist[i];
            if (v > best) { best = v; bi = i; }   // strict > keeps lowest idx
        }
#pragma unroll
        for (int off = 16; off; off >>= 1) {
            float ov = __shfl_xor_sync(0xffffffffu, best, off);
            int   oi = __shfl_xor_sync(0xffffffffu, bi,   off);
            if (ov > best || (ov == best && oi < bi)) { best = ov; bi = oi; }
        }
        if (lane == 0) dist[bi] = -FLT_MAX;
        __syncwarp();
        int ix = bi / FH, iy = bi % FH;
        minx = min(minx, ix); maxx = max(maxx, ix);
        miny = min(miny, iy); maxy = max(maxy, iy);
    }
    if (lane == 0) {
        int x_i = minx * PATCH, x_f = maxx * PATCH;
        int y_i = miny * PATCH, y_f = maxy * PATCH;
        g_box[b][0] = max(x_i, 0);
        g_box[b][1] = min(max(x_f, x_i + PATCH), IMG);
        g_box[b][2] = max(y_i, 0);
        g_box[b][3] = min(max(y_f, y_i + PATCH), IMG);
    }
}

// ---------------------------------------------------------------------------
// Kernel 3: register-rolling separable bilinear crop-resize.
// Block = (b, c, group of 8 output rows), 448 threads = one per column.
// Each thread fixes its horizontal taps (xlo/xhi/wx) once, keeps the two
// horizontally-lerped source-row values (h0, h1) in REGISTERS, and rolls
// them forward as ylo advances (block-uniform, <=1 per output row since
// vertical slope <= 1). Each needed source row is loaded exactly once per
// column via 2 near-coalesced scalar LDGs. No smem, no __syncthreads.
// Per output pixel: ~3 FMA + 1 coalesced STG.32.
// ---------------------------------------------------------------------------
#define ROWG 8
__global__ void __launch_bounds__(448) resize_kernel(
        const float* __restrict__ images, float* __restrict__ out) {
    int blk = blockIdx.x;
    int g  = blk % (IMG / ROWG);
    int t  = blk / (IMG / ROWG);
    int c  = t % 3;
    int b  = t / 3;
    int ty0 = g * ROWG;
    int tx  = threadIdx.x;                    // output column, 0..447

    int4 bx = *(const int4*)&g_box[b][0];
    int x0 = bx.x, x1 = bx.y, y0 = bx.z, y1 = bx.w;

    const float scale = 1.0f / (float)(IMG - 1);
    float hstep = ((float)(x1 - x0) - 1.0f) * scale;   // <= 1
    float wstep = ((float)(y1 - y0) - 1.0f) * scale;

    // horizontal taps: fixed for this thread
    float sx  = (float)y0 + (float)tx * wstep;
    int   xlo = (int)floorf(sx);
    int   xhi = min(xlo + 1, y1 - 1);
    float wx  = sx - (float)xlo;

    const float* src = images + (size_t)(b * 3 + c) * IMG * IMG;
    float x0f = (float)x0;

    // initial vertical rows for output row ty0
    int   cr = (int)floorf(x0f + (float)ty0 * hstep);  // current base row
    {
        const float* r0 = src + (size_t)cr * IMG;
        int nr = min(cr + 1, x1 - 1);
        const float* r1 = src + (size_t)nr * IMG;
        // fallthrough into h0/h1 below
    }
    const float* rp = src + (size_t)cr * IMG;
    float a0 = __ldg(rp + xlo), b0 = __ldg(rp + xhi);
    float h0 = a0 + wx * (b0 - a0);
    int nr = min(cr + 1, x1 - 1);
    const float* rq = src + (size_t)nr * IMG;
    float a1 = __ldg(rq + xlo), b1 = __ldg(rq + xhi);
    float h1 = a1 + wx * (b1 - a1);

    float* ob = out + ((size_t)(b * 3 + c) * IMG + ty0) * IMG + tx;
#pragma unroll
    for (int rr = 0; rr < ROWG; ++rr) {
        float sy  = x0f + (float)(ty0 + rr) * hstep;
        int   ylo = (int)floorf(sy);
        float wy  = sy - (float)ylo;
        // roll forward (block-uniform; executes 0 or 1 times)
        while (ylo > cr) {
            ++cr;
            h0 = h1;
            int nx = min(cr + 1, x1 - 1);
            const float* rn = src + (size_t)nx * IMG;
            float an = __ldg(rn + xlo), bn = __ldg(rn + xhi);
            h1 = an + wx * (bn - an);
        }
        ob[(size_t)rr * IMG] = h0 + wy * (h1 - h0);
    }
}

// ---------------------------------------------------------------------------
extern "C" void kernel_launch(void* const* d_in, const int* in_sizes, int n_in,
                              void* d_out, int out_size) {
    const float* x      = (const float*)d_in[0];
    const float* images = (const float*)d_in[1];
    const int X_ELEMS   = NB * 785 * DIM;
    if (n_in >= 2 && in_sizes[0] != X_ELEMS) {
        x      = (const float*)d_in[1];
        images = (const float*)d_in[0];
    }
    float* out = (float*)d_out;

    dim3 g1(NB, 49);
    sim_kernel<<<g1, 256>>>(x);
    topk_kernel<<<NB, 32>>>();
    resize_kernel<<<NB * 3 * (IMG / ROWG), 448>>>(images, out);
}

// round 9
// speedup vs baseline: 1.2941x; 1.2941x over previous
#include <cuda_runtime.h>
#include <math.h>
#include <float.h>

#define NB      64
#define TOKENS  784
#define DIM     768
#define FH      28
#define IMG     448
#define TOPK    8
#define PATCH   16

__device__ float g_dist[NB * TOKENS];
__device__ int   g_box[NB][4];   // x0, x1, y0, y1

// ---------------------------------------------------------------------------
// Kernel 1: score = dot(g, l) / ||l||  (g-norm positive per-batch constant
// -> same ordering as cosine). grid (64,49) x 256, 2 rows per warp.
// ---------------------------------------------------------------------------
__global__ void __launch_bounds__(256) sim_kernel(const float* __restrict__ x) {
    int b = blockIdx.x;
    int s = blockIdx.y;                       // 0..48 -> 16 rows per block
    const float* xb = x + (size_t)b * 785 * DIM;

    __shared__ float4 g_sh[DIM / 4];          // CLS token, 3 KB
    int tid = threadIdx.x;
    if (tid < DIM / 4) g_sh[tid] = ((const float4*)xb)[tid];
    __syncthreads();

    int warp = tid >> 5, lane = tid & 31;
    int r = s * 16 + warp * 2;                // this warp's row pair
    const float4* l0 = (const float4*)(xb + (size_t)(1 + r) * DIM);
    const float4* l1 = (const float4*)(xb + (size_t)(2 + r) * DIM);
    float d0 = 0.f, n0 = 0.f, d1 = 0.f, n1 = 0.f;
#pragma unroll
    for (int j = 0; j < 6; ++j) {
        float4 a = l0[lane + 32 * j];
        float4 c = l1[lane + 32 * j];
        float4 g = g_sh[lane + 32 * j];
        d0 += a.x * g.x + a.y * g.y + a.z * g.z + a.w * g.w;
        n0 += a.x * a.x + a.y * a.y + a.z * a.z + a.w * a.w;
        d1 += c.x * g.x + c.y * g.y + c.z * g.z + c.w * g.w;
        n1 += c.x * c.x + c.y * c.y + c.z * c.z + c.w * c.w;
    }
#pragma unroll
    for (int off = 16; off; off >>= 1) {
        d0 += __shfl_xor_sync(0xffffffffu, d0, off);
        n0 += __shfl_xor_sync(0xffffffffu, n0, off);
        d1 += __shfl_xor_sync(0xffffffffu, d1, off);
        n1 += __shfl_xor_sync(0xffffffffu, n1, off);
    }
    if (lane == 0) {
        g_dist[b * TOKENS + r]     = d0 / fmaxf(sqrtf(n0), 1e-8f);
        g_dist[b * TOKENS + r + 1] = d1 / fmaxf(sqrtf(n1), 1e-8f);
    }
}

// ---------------------------------------------------------------------------
// Kernel 2: top-8 argmax rounds (stable ties -> lower index), bounding box.
// ---------------------------------------------------------------------------
__global__ void topk_kernel() {
    int b = blockIdx.x;
    int lane = threadIdx.x;                   // 32 threads
    __shared__ float dist[TOKENS];
    for (int i = lane; i < TOKENS; i += 32) dist[i] = g_dist[b * TOKENS + i];
    __syncwarp();

    int minx = FH, maxx = -1, miny = FH, maxy = -1;
#pragma unroll 1
    for (int k = 0; k < TOPK; ++k) {
        float best = -FLT_MAX; int bi = TOKENS;
        for (int i = lane; i < TOKENS; i += 32) {
            float v = dist[i];
            if (v > best) { best = v; bi = i; }   // strict > keeps lowest idx
        }
#pragma unroll
        for (int off = 16; off; off >>= 1) {
            float ov = __shfl_xor_sync(0xffffffffu, best, off);
            int   oi = __shfl_xor_sync(0xffffffffu, bi,   off);
            if (ov > best || (ov == best && oi < bi)) { best = ov; bi = oi; }
        }
        if (lane == 0) dist[bi] = -FLT_MAX;
        __syncwarp();
        int ix = bi / FH, iy = bi % FH;
        minx = min(minx, ix); maxx = max(maxx, ix);
        miny = min(miny, iy); maxy = max(maxy, iy);
    }
    if (lane == 0) {
        int x_i = minx * PATCH, x_f = maxx * PATCH;
        int y_i = miny * PATCH, y_f = maxy * PATCH;
        g_box[b][0] = max(x_i, 0);
        g_box[b][1] = min(max(x_f, x_i + PATCH), IMG);
        g_box[b][2] = max(y_i, 0);
        g_box[b][3] = min(max(y_f, y_i + PATCH), IMG);
    }
}

// ---------------------------------------------------------------------------
// Kernel 3: separable bilinear crop-resize, direct-from-gmem horizontal pass.
// Block = (b, c, 8 output rows) -> at most 9 source rows (vertical slope<=1).
// Phase A: horizontal lerp straight from GLOBAL into hrow[r][448]. Per
//   column thread: 9 rows x 2 near-unit-stride LDGs, all independent
//   (MLP ~18/thread; a warp's 32 taps span <=33 floats = ~2 sectors).
// Phase B: vertical lerp, float4-vectorized from smem: 2 x LDS.128 + 4 FMA
//   + STG.128 per output quad.
// vs R4: removes the entire gmem->smem staging phase + one syncthreads and
// halves smem (16.1 KB -> 8 blocks/SM).
// ---------------------------------------------------------------------------
#define ROWG 8
__global__ void __launch_bounds__(256) resize_kernel(
        const float* __restrict__ images, float* __restrict__ out) {
    int blk = blockIdx.x;
    int g  = blk % (IMG / ROWG);
    int t  = blk / (IMG / ROWG);
    int c  = t % 3;
    int b  = t / 3;
    int ty0 = g * ROWG;

    __shared__ float hrow[9 * IMG];           // 16.1 KB

    int4 bx = *(const int4*)&g_box[b][0];
    int x0 = bx.x, x1 = bx.y, y0 = bx.z, y1 = bx.w;

    const float scale = 1.0f / (float)(IMG - 1);
    float hstep = ((float)(x1 - x0) - 1.0f) * scale;   // <= 1
    float wstep = ((float)(y1 - y0) - 1.0f) * scale;

    int rlo = (int)floorf((float)x0 + (float)ty0 * hstep);
    int rhi = min((int)floorf((float)x0 + (float)(ty0 + ROWG - 1) * hstep) + 1,
                  x1 - 1);
    int nrows = rhi - rlo + 1;                // <= 9

    const float* src = images + (size_t)(b * 3 + c) * IMG * IMG;
    int tid = threadIdx.x;

    // Phase A: horizontal lerp from global (2 cols per thread)
    for (int col = tid; col < IMG; col += 256) {
        float sx  = (float)y0 + (float)col * wstep;
        int   xlo = (int)floorf(sx);
        int   xhi = min(xlo + 1, y1 - 1);
        float wx  = sx - (float)xlo;
        const float* p = src + (size_t)rlo * IMG;
#pragma unroll
        for (int rr = 0; rr < 9; ++rr) {
            if (rr < nrows) {
                float a  = __ldg(p + (size_t)rr * IMG + xlo);
                float bv = __ldg(p + (size_t)rr * IMG + xhi);
                hrow[rr * IMG + col] = a + wx * (bv - a);
            }
        }
    }
    __syncthreads();

    // Phase B: vertical lerp, float4-vectorized
    float* obase = out + (size_t)(b * 3 + c) * IMG * IMG;
#pragma unroll 1
    for (int j = tid; j < ROWG * (IMG / 4); j += 256) {
        int tyl = j / (IMG / 4);
        int txq = j - tyl * (IMG / 4);
        int ty  = ty0 + tyl;

        float sy  = (float)x0 + (float)ty * hstep;
        int   ylo = (int)floorf(sy);
        int   yhi = min(ylo + 1, x1 - 1);
        float wy  = sy - (float)ylo;

        float4 h0 = ((const float4*)(hrow + (ylo - rlo) * IMG))[txq];
        float4 h1 = ((const float4*)(hrow + (yhi - rlo) * IMG))[txq];
        float4 res;
        res.x = h0.x + wy * (h1.x - h0.x);
        res.y = h0.y + wy * (h1.y - h0.y);
        res.z = h0.z + wy * (h1.z - h0.z);
        res.w = h0.w + wy * (h1.w - h0.w);
        ((float4*)(obase + (size_t)ty * IMG))[txq] = res;
    }
}

// ---------------------------------------------------------------------------
extern "C" void kernel_launch(void* const* d_in, const int* in_sizes, int n_in,
                              void* d_out, int out_size) {
    const float* x      = (const float*)d_in[0];
    const float* images = (const float*)d_in[1];
    const int X_ELEMS   = NB * 785 * DIM;
    if (n_in >= 2 && in_sizes[0] != X_ELEMS) {
        x      = (const float*)d_in[1];
        images = (const float*)d_in[0];
    }
    float* out = (float*)d_out;

    dim3 g1(NB, 49);
    sim_kernel<<<g1, 256>>>(x);
    topk_kernel<<<NB, 32>>>();
    resize_kernel<<<NB * 3 * (IMG / ROWG), 256>>>(images, out);
}

// round 10
// speedup vs baseline: 1.3570x; 1.0486x over previous
#include <cuda_runtime.h>
#include <math.h>
#include <float.h>

#define NB      64
#define TOKENS  784
#define DIM     768
#define FH      28
#define IMG     448
#define TOPK    8
#define PATCH   16

__device__ float g_dist[NB * TOKENS];
__device__ int   g_box[NB][4];   // x0, x1, y0, y1

// ---------------------------------------------------------------------------
// Kernel 1: score = dot(g, l) / ||l||  (g-norm positive per-batch constant
// -> same ordering as cosine). grid (64,49) x 256, 2 rows per warp.
// ---------------------------------------------------------------------------
__global__ void __launch_bounds__(256) sim_kernel(const float* __restrict__ x) {
    int b = blockIdx.x;
    int s = blockIdx.y;                       // 0..48 -> 16 rows per block
    const float* xb = x + (size_t)b * 785 * DIM;

    __shared__ float4 g_sh[DIM / 4];          // CLS token, 3 KB
    int tid = threadIdx.x;
    if (tid < DIM / 4) g_sh[tid] = ((const float4*)xb)[tid];
    __syncthreads();

    int warp = tid >> 5, lane = tid & 31;
    int r = s * 16 + warp * 2;                // this warp's row pair
    const float4* l0 = (const float4*)(xb + (size_t)(1 + r) * DIM);
    const float4* l1 = (const float4*)(xb + (size_t)(2 + r) * DIM);
    float d0 = 0.f, n0 = 0.f, d1 = 0.f, n1 = 0.f;
#pragma unroll
    for (int j = 0; j < 6; ++j) {
        float4 a = l0[lane + 32 * j];
        float4 c = l1[lane + 32 * j];
        float4 g = g_sh[lane + 32 * j];
        d0 += a.x * g.x + a.y * g.y + a.z * g.z + a.w * g.w;
        n0 += a.x * a.x + a.y * a.y + a.z * a.z + a.w * a.w;
        d1 += c.x * g.x + c.y * g.y + c.z * g.z + c.w * g.w;
        n1 += c.x * c.x + c.y * c.y + c.z * c.z + c.w * c.w;
    }
#pragma unroll
    for (int off = 16; off; off >>= 1) {
        d0 += __shfl_xor_sync(0xffffffffu, d0, off);
        n0 += __shfl_xor_sync(0xffffffffu, n0, off);
        d1 += __shfl_xor_sync(0xffffffffu, d1, off);
        n1 += __shfl_xor_sync(0xffffffffu, n1, off);
    }
    if (lane == 0) {
        g_dist[b * TOKENS + r]     = d0 / fmaxf(sqrtf(n0), 1e-8f);
        g_dist[b * TOKENS + r + 1] = d1 / fmaxf(sqrtf(n1), 1e-8f);
    }
}

// ---------------------------------------------------------------------------
// Kernel 2: top-8 argmax rounds (stable ties -> lower index), bounding box.
// ---------------------------------------------------------------------------
__global__ void topk_kernel() {
    int b = blockIdx.x;
    int lane = threadIdx.x;                   // 32 threads
    __shared__ float dist[TOKENS];
    for (int i = lane; i < TOKENS; i += 32) dist[i] = g_dist[b * TOKENS + i];
    __syncwarp();

    int minx = FH, maxx = -1, miny = FH, maxy = -1;
#pragma unroll 1
    for (int k = 0; k < TOPK; ++k) {
        float best = -FLT_MAX; int bi = TOKENS;
        for (int i = lane; i < TOKENS; i += 32) {
            float v = dist[i];
            if (v > best) { best = v; bi = i; }   // strict > keeps lowest idx
        }
#pragma unroll
        for (int off = 16; off; off >>= 1) {
            float ov = __shfl_xor_sync(0xffffffffu, best, off);
            int   oi = __shfl_xor_sync(0xffffffffu, bi,   off);
            if (ov > best || (ov == best && oi < bi)) { best = ov; bi = oi; }
        }
        if (lane == 0) dist[bi] = -FLT_MAX;
        __syncwarp();
        int ix = bi / FH, iy = bi % FH;
        minx = min(minx, ix); maxx = max(maxx, ix);
        miny = min(miny, iy); maxy = max(maxy, iy);
    }
    if (lane == 0) {
        int x_i = minx * PATCH, x_f = maxx * PATCH;
        int y_i = miny * PATCH, y_f = maxy * PATCH;
        g_box[b][0] = max(x_i, 0);
        g_box[b][1] = min(max(x_f, x_i + PATCH), IMG);
        g_box[b][2] = max(y_i, 0);
        g_box[b][3] = min(max(y_f, y_i + PATCH), IMG);
    }
}

// ---------------------------------------------------------------------------
// Kernel 3: separable bilinear crop-resize, direct-from-gmem horizontal pass.
// Block = (b, c, 16 output rows), 448 threads = exactly one output column
// each. 16 output rows touch at most 17 source rows (vertical slope <= 1).
// Phase A: horizontal lerp straight from GLOBAL into hrow[r][448]: per
//   thread 17 rows x 2 near-unit-stride LDGs, all independent (MLP ~34;
//   a warp's 32 taps span <=33 floats = ~2 sectors).
// Phase B: vertical lerp, float4-vectorized from smem: 2 x LDS.128 + 4 FMA
//   + STG.128 per output quad, 4 quads per thread.
// vs R6 (ROWG=8/256T): half the blocks -> half the per-block setup/sync and
// boundary-row re-reads; 2x phase-A MLP; no column-loop remainder pass.
// ---------------------------------------------------------------------------
#define ROWG 16
__global__ void __launch_bounds__(448) resize_kernel(
        const float* __restrict__ images, float* __restrict__ out) {
    int blk = blockIdx.x;
    int g  = blk % (IMG / ROWG);
    int t  = blk / (IMG / ROWG);
    int c  = t % 3;
    int b  = t / 3;
    int ty0 = g * ROWG;
    int tid = threadIdx.x;                    // output column, 0..447

    __shared__ float hrow[(ROWG + 1) * IMG];  // 17*448*4 = 29.8 KB

    int4 bx = *(const int4*)&g_box[b][0];
    int x0 = bx.x, x1 = bx.y, y0 = bx.z, y1 = bx.w;

    const float scale = 1.0f / (float)(IMG - 1);
    float hstep = ((float)(x1 - x0) - 1.0f) * scale;   // <= 1
    float wstep = ((float)(y1 - y0) - 1.0f) * scale;

    int rlo = (int)floorf((float)x0 + (float)ty0 * hstep);
    int rhi = min((int)floorf((float)x0 + (float)(ty0 + ROWG - 1) * hstep) + 1,
                  x1 - 1);
    int nrows = rhi - rlo + 1;                // <= 17

    const float* src = images + (size_t)(b * 3 + c) * IMG * IMG;

    // Phase A: horizontal lerp from global, one column per thread
    {
        float sx  = (float)y0 + (float)tid * wstep;
        int   xlo = (int)floorf(sx);
        int   xhi = min(xlo + 1, y1 - 1);
        float wx  = sx - (float)xlo;
        const float* p = src + (size_t)rlo * IMG;
#pragma unroll
        for (int rr = 0; rr < ROWG + 1; ++rr) {
            if (rr < nrows) {
                float a  = __ldg(p + (size_t)rr * IMG + xlo);
                float bv = __ldg(p + (size_t)rr * IMG + xhi);
                hrow[rr * IMG + tid] = a + wx * (bv - a);
            }
        }
    }
    __syncthreads();

    // Phase B: vertical lerp, float4-vectorized (4 quads per thread)
    float* obase = out + (size_t)(b * 3 + c) * IMG * IMG;
#pragma unroll
    for (int it = 0; it < ROWG * (IMG / 4) / 448; ++it) {
        int j = tid + it * 448;
        int tyl = j / (IMG / 4);
        int txq = j - tyl * (IMG / 4);
        int ty  = ty0 + tyl;

        float sy  = (float)x0 + (float)ty * hstep;
        int   ylo = (int)floorf(sy);
        int   yhi = min(ylo + 1, x1 - 1);
        float wy  = sy - (float)ylo;

        float4 h0 = ((const float4*)(hrow + (ylo - rlo) * IMG))[txq];
        float4 h1 = ((const float4*)(hrow + (yhi - rlo) * IMG))[txq];
        float4 res;
        res.x = h0.x + wy * (h1.x - h0.x);
        res.y = h0.y + wy * (h1.y - h0.y);
        res.z = h0.z + wy * (h1.z - h0.z);
        res.w = h0.w + wy * (h1.w - h0.w);
        ((float4*)(obase + (size_t)ty * IMG))[txq] = res;
    }
}

// ---------------------------------------------------------------------------
extern "C" void kernel_launch(void* const* d_in, const int* in_sizes, int n_in,
                              void* d_out, int out_size) {
    const float* x      = (const float*)d_in[0];
    const float* images = (const float*)d_in[1];
    const int X_ELEMS   = NB * 785 * DIM;
    if (n_in >= 2 && in_sizes[0] != X_ELEMS) {
        x      = (const float*)d_in[1];
        images = (const float*)d_in[0];
    }
    float* out = (float*)d_out;

    dim3 g1(NB, 49);
    sim_kernel<<<g1, 256>>>(x);
    topk_kernel<<<NB, 32>>>();
    resize_kernel<<<NB * 3 * (IMG / ROWG), 448>>>(images, out);
}

// round 11
// speedup vs baseline: 1.4173x; 1.0445x over previous
#include <cuda_runtime.h>
#include <math.h>
#include <float.h>

#define NB      64
#define TOKENS  784
#define DIM     768
#define FH      28
#define IMG     448
#define TOPK    8
#define PATCH   16

__device__ float g_dist[NB * TOKENS];
__device__ int   g_box[NB][4];   // x0, x1, y0, y1

// ---------------------------------------------------------------------------
// Kernel 1: score = dot(g, l) / ||l||  (g-norm positive per-batch constant
// -> same ordering as cosine). grid (64,49) x 256, 2 rows per warp.
// x is touched exactly once -> streaming (evict-first) loads.
// ---------------------------------------------------------------------------
__global__ void __launch_bounds__(256) sim_kernel(const float* __restrict__ x) {
    int b = blockIdx.x;
    int s = blockIdx.y;                       // 0..48 -> 16 rows per block
    const float* xb = x + (size_t)b * 785 * DIM;

    __shared__ float4 g_sh[DIM / 4];          // CLS token, 3 KB
    int tid = threadIdx.x;
    if (tid < DIM / 4) g_sh[tid] = ((const float4*)xb)[tid];
    __syncthreads();

    int warp = tid >> 5, lane = tid & 31;
    int r = s * 16 + warp * 2;                // this warp's row pair
    const float4* l0 = (const float4*)(xb + (size_t)(1 + r) * DIM);
    const float4* l1 = (const float4*)(xb + (size_t)(2 + r) * DIM);
    float d0 = 0.f, n0 = 0.f, d1 = 0.f, n1 = 0.f;
#pragma unroll
    for (int j = 0; j < 6; ++j) {
        float4 a = __ldcs(l0 + lane + 32 * j);
        float4 c = __ldcs(l1 + lane + 32 * j);
        float4 g = g_sh[lane + 32 * j];
        d0 += a.x * g.x + a.y * g.y + a.z * g.z + a.w * g.w;
        n0 += a.x * a.x + a.y * a.y + a.z * a.z + a.w * a.w;
        d1 += c.x * g.x + c.y * g.y + c.z * g.z + c.w * g.w;
        n1 += c.x * c.x + c.y * c.y + c.z * c.z + c.w * c.w;
    }
#pragma unroll
    for (int off = 16; off; off >>= 1) {
        d0 += __shfl_xor_sync(0xffffffffu, d0, off);
        n0 += __shfl_xor_sync(0xffffffffu, n0, off);
        d1 += __shfl_xor_sync(0xffffffffu, d1, off);
        n1 += __shfl_xor_sync(0xffffffffu, n1, off);
    }
    if (lane == 0) {
        g_dist[b * TOKENS + r]     = d0 / fmaxf(sqrtf(n0), 1e-8f);
        g_dist[b * TOKENS + r + 1] = d1 / fmaxf(sqrtf(n1), 1e-8f);
    }
}

// ---------------------------------------------------------------------------
// Kernel 2: top-8 argmax rounds (stable ties -> lower index), bounding box.
// ---------------------------------------------------------------------------
__global__ void topk_kernel() {
    int b = blockIdx.x;
    int lane = threadIdx.x;                   // 32 threads
    __shared__ float dist[TOKENS];
    for (int i = lane; i < TOKENS; i += 32) dist[i] = g_dist[b * TOKENS + i];
    __syncwarp();

    int minx = FH, maxx = -1, miny = FH, maxy = -1;
#pragma unroll 1
    for (int k = 0; k < TOPK; ++k) {
        float best = -FLT_MAX; int bi = TOKENS;
        for (int i = lane; i < TOKENS; i += 32) {
            float v = dist[i];
            if (v > best) { best = v; bi = i; }   // strict > keeps lowest idx
        }
#pragma unroll
        for (int off = 16; off; off >>= 1) {
            float ov = __shfl_xor_sync(0xffffffffu, best, off);
            int   oi = __shfl_xor_sync(0xffffffffu, bi,   off);
            if (ov > best || (ov == best && oi < bi)) { best = ov; bi = oi; }
        }
        if (lane == 0) dist[bi] = -FLT_MAX;
        __syncwarp();
        int ix = bi / FH, iy = bi % FH;
        minx = min(minx, ix); maxx = max(maxx, ix);
        miny = min(miny, iy); maxy = max(maxy, iy);
    }
    if (lane == 0) {
        int x_i = minx * PATCH, x_f = maxx * PATCH;
        int y_i = miny * PATCH, y_f = maxy * PATCH;
        g_box[b][0] = max(x_i, 0);
        g_box[b][1] = min(max(x_f, x_i + PATCH), IMG);
        g_box[b][2] = max(y_i, 0);
        g_box[b][3] = min(max(y_f, y_i + PATCH), IMG);
    }
}

// ---------------------------------------------------------------------------
// Kernel 3: separable bilinear crop-resize, warp-autonomous.
// Block = (b, c, 16 output rows), 448 threads / 14 warps. Each warp owns a
// 32-column output window for BOTH phases, so only __syncwarp() is needed —
// no warp ever waits on another warp's DRAM latency tail.
// Phase A: horizontal lerp from GLOBAL into hrow[r][own 32 cols]
//   (17 rows x 2 near-unit-stride independent LDGs per thread).
// Phase B: vertical lerp over own window: per iteration 8 lanes cover one
//   row's 8 float4 quads (contiguous 128B LDS + STG.128), 4 iterations.
// Output stored with __stcs (evict-first): written once, never re-read ->
// keeps L2 free for crop reads.
// ---------------------------------------------------------------------------
#define ROWG 16
__global__ void __launch_bounds__(448) resize_kernel(
        const float* __restrict__ images, float* __restrict__ out) {
    int blk = blockIdx.x;
    int g  = blk % (IMG / ROWG);
    int t  = blk / (IMG / ROWG);
    int c  = t % 3;
    int b  = t / 3;
    int ty0 = g * ROWG;
    int tid  = threadIdx.x;
    int warp = tid >> 5;                      // 0..13
    int lane = tid & 31;
    int col  = (warp << 5) + lane;            // this thread's output column

    __shared__ __align__(16) float hrow[(ROWG + 1) * IMG];  // 29.8 KB

    int4 bx = *(const int4*)&g_box[b][0];
    int x0 = bx.x, x1 = bx.y, y0 = bx.z, y1 = bx.w;

    const float scale = 1.0f / (float)(IMG - 1);
    float hstep = ((float)(x1 - x0) - 1.0f) * scale;   // <= 1
    float wstep = ((float)(y1 - y0) - 1.0f) * scale;

    int rlo = (int)floorf((float)x0 + (float)ty0 * hstep);
    int rhi = min((int)floorf((float)x0 + (float)(ty0 + ROWG - 1) * hstep) + 1,
                  x1 - 1);
    int nrows = rhi - rlo + 1;                // <= 17

    const float* src = images + (size_t)(b * 3 + c) * IMG * IMG;

    // Phase A: horizontal lerp from global, one column per thread
    {
        float sx  = (float)y0 + (float)col * wstep;
        int   xlo = (int)floorf(sx);
        int   xhi = min(xlo + 1, y1 - 1);
        float wx  = sx - (float)xlo;
        const float* p = src + (size_t)rlo * IMG;
#pragma unroll
        for (int rr = 0; rr < ROWG + 1; ++rr) {
            if (rr < nrows) {
                float a  = __ldg(p + (size_t)rr * IMG + xlo);
                float bv = __ldg(p + (size_t)rr * IMG + xhi);
                hrow[rr * IMG + col] = a + wx * (bv - a);
            }
        }
    }
    __syncwarp();

    // Phase B: vertical lerp over this warp's 32-column window.
    // j = it*32 + lane; row = j/8 within this it-batch of 4 rows;
    // quad = warp*8 + (j%8).
    float* obase = out + (size_t)(b * 3 + c) * IMG * IMG;
#pragma unroll
    for (int it = 0; it < ROWG / 4; ++it) {
        int j   = (it << 5) + lane;
        int tyl = j >> 3;                     // 0..15 across the 4 its
        int q   = j & 7;
        int txq = (warp << 3) + q;            // quad index in [warp*8, warp*8+8)
        int ty  = ty0 + tyl;

        float sy  = (float)x0 + (float)ty * hstep;
        int   ylo = (int)floorf(sy);
        int   yhi = min(ylo + 1, x1 - 1);
        float wy  = sy - (float)ylo;

        float4 h0 = ((const float4*)(hrow + (ylo - rlo) * IMG))[txq];
        float4 h1 = ((const float4*)(hrow + (yhi - rlo) * IMG))[txq];
        float4 res;
        res.x = h0.x + wy * (h1.x - h0.x);
        res.y = h0.y + wy * (h1.y - h0.y);
        res.z = h0.z + wy * (h1.z - h0.z);
        res.w = h0.w + wy * (h1.w - h0.w);
        __stcs((float4*)(obase + (size_t)ty * IMG) + txq, res);
    }
}

// ---------------------------------------------------------------------------
extern "C" void kernel_launch(void* const* d_in, const int* in_sizes, int n_in,
                              void* d_out, int out_size) {
    const float* x      = (const float*)d_in[0];
    const float* images = (const float*)d_in[1];
    const int X_ELEMS   = NB * 785 * DIM;
    if (n_in >= 2 && in_sizes[0] != X_ELEMS) {
        x      = (const float*)d_in[1];
        images = (const float*)d_in[0];
    }
    float* out = (float*)d_out;

    dim3 g1(NB, 49);
    sim_kernel<<<g1, 256>>>(x);
    topk_kernel<<<NB, 32>>>();
    resize_kernel<<<NB * 3 * (IMG / ROWG), 448>>>(images, out);
}